// round 3
// baseline (speedup 1.0000x reference)
#include <cuda_runtime.h>
#include <cuda_bf16.h>

#define B_ 8
#define N_ 1024
#define C_ 256
#define HD_ 256   // H*D
#define NEG_SLOPE 0.2f

// Scratch (no cudaMalloc allowed)
__device__ float g_Wx[B_ * N_ * HD_];      // 32MB
__device__ float g_ei[B_ * N_ * 4];
__device__ float g_ej[B_ * N_ * 4];

// ---------------------------------------------------------------------------
// Kernel 1: Wx = x @ W   (M=8192, K=256, N=256)
// BM=128, BN=128, BK=16, 256 threads, TM=8, TN=8, As transposed [k][m]
// grid = (64, 2) = 128 blocks ~ one wave on 148 SMs
// ---------------------------------------------------------------------------
__global__ void gemm_kernel(const float* __restrict__ A,
                            const float* __restrict__ Bm,
                            float* __restrict__ Cm) {
    __shared__ float As[16][132];   // [k][m], pad->132 keeps float4 alignment
    __shared__ float Bs[16][128];   // [k][n]

    const int tid = threadIdx.x;
    const int rowBase = blockIdx.x * 128;
    const int colBase = blockIdx.y * 128;

    const int tx = tid & 15;        // 16 col groups * TN=8 -> 128
    const int ty = tid >> 4;        // 16 row groups * TM=8 -> 128

    float acc[8][8];
#pragma unroll
    for (int i = 0; i < 8; i++)
#pragma unroll
        for (int j = 0; j < 8; j++) acc[i][j] = 0.f;

    for (int kb = 0; kb < C_; kb += 16) {
        // load A tile 128x16 -> transposed into As[k][m]
#pragma unroll
        for (int u = 0; u < 2; u++) {
            int f = tid + u * 256;          // 512 float4s
            int row = f >> 2;
            int c0 = (f & 3) * 4;
            float4 v = *(const float4*)(A + (size_t)(rowBase + row) * C_ + kb + c0);
            As[c0 + 0][row] = v.x;
            As[c0 + 1][row] = v.y;
            As[c0 + 2][row] = v.z;
            As[c0 + 3][row] = v.w;
        }
        // load B tile 16x128
#pragma unroll
        for (int u = 0; u < 2; u++) {
            int f = tid + u * 256;          // 512 float4s
            int r = f >> 5;
            int cq = f & 31;
            float4 v = *(const float4*)(Bm + (size_t)(kb + r) * HD_ + colBase + cq * 4);
            *(float4*)(&Bs[r][cq * 4]) = v;
        }
        __syncthreads();

#pragma unroll
        for (int k = 0; k < 16; k++) {
            float4 a0 = *(const float4*)(&As[k][ty * 8]);
            float4 a1 = *(const float4*)(&As[k][ty * 8 + 4]);
            float4 b0 = *(const float4*)(&Bs[k][tx * 8]);
            float4 b1 = *(const float4*)(&Bs[k][tx * 8 + 4]);
            float av[8] = {a0.x, a0.y, a0.z, a0.w, a1.x, a1.y, a1.z, a1.w};
            float bv[8] = {b0.x, b0.y, b0.z, b0.w, b1.x, b1.y, b1.z, b1.w};
#pragma unroll
            for (int i = 0; i < 8; i++)
#pragma unroll
                for (int j = 0; j < 8; j++)
                    acc[i][j] += av[i] * bv[j];
        }
        __syncthreads();
    }
#pragma unroll
    for (int i = 0; i < 8; i++) {
        float* dst = Cm + (size_t)(rowBase + ty * 8 + i) * HD_ + colBase + tx * 8;
        *(float4*)(dst)     = make_float4(acc[i][0], acc[i][1], acc[i][2], acc[i][3]);
        *(float4*)(dst + 4) = make_float4(acc[i][4], acc[i][5], acc[i][6], acc[i][7]);
    }
}

// ---------------------------------------------------------------------------
// Kernel 2: e_i/e_j projections.  One block per (b,n) row, 256 threads.
// ---------------------------------------------------------------------------
__global__ void eij_kernel(const float* __restrict__ a,
                           const float* __restrict__ Wx,
                           float* __restrict__ ei, float* __restrict__ ej) {
    const int row = blockIdx.x;
    const int t = threadIdx.x;
    const int h = t >> 6, d = t & 63;

    float wx = Wx[(size_t)row * HD_ + t];
    float vi = wx * a[h * 128 + d];
    float vj = wx * a[h * 128 + 64 + d];

    const int lane = t & 31;
#pragma unroll
    for (int o = 16; o > 0; o >>= 1) {
        vi += __shfl_xor_sync(0xffffffffu, vi, o);
        vj += __shfl_xor_sync(0xffffffffu, vj, o);
    }
    __shared__ float si[8], sj[8];
    const int w = t >> 5;
    if (lane == 0) { si[w] = vi; sj[w] = vj; }
    __syncthreads();
    if (t < 4) {
        ei[row * 4 + t] = si[t * 2] + si[t * 2 + 1];
        ej[row * 4 + t] = sj[t * 2] + sj[t * 2 + 1];
    }
}

// ---------------------------------------------------------------------------
// Kernel 3: sparse-compact softmax + aggregation.  Block per (b,n).
// No max-subtraction: e = ei+ej is O(5) in magnitude, exp cannot overflow,
// and softmax is shift-invariant.
// ---------------------------------------------------------------------------
__global__ void __launch_bounds__(256)
gat_kernel(const float* __restrict__ adj,
           const float* __restrict__ Wx,
           const float* __restrict__ ei,
           const float* __restrict__ ej,
           float* __restrict__ out) {
    const int b = blockIdx.x >> 10;
    const int n = blockIdx.x & 1023;
    const int t = threadIdx.x;
    const int lane = t & 31, w = t >> 5;

    __shared__ unsigned short s_idx[N_];
    __shared__ float s_e[N_ * 4];          // exp(e) per neighbor, 4 heads
    __shared__ float s_red[256 * 4];       // group partials (float4 view)
    __shared__ int   s_warp[8];
    __shared__ int   s_off[9];
    __shared__ float4 s_wred[8];
    __shared__ float4 s_bcast;

    const float* adj_row = adj + ((size_t)(b * N_ + n)) * N_;

    // --- deterministic compaction of nonzero neighbors (incl. self) ---
    const int jb = t * 4;
    float4 av4 = *(const float4*)(adj_row + jb);
    bool p[4];
    p[0] = (av4.x != 0.f) || (jb + 0 == n);
    p[1] = (av4.y != 0.f) || (jb + 1 == n);
    p[2] = (av4.z != 0.f) || (jb + 2 == n);
    p[3] = (av4.w != 0.f) || (jb + 3 == n);
    int cnt = (p[0] ? 1 : 0) + (p[1] ? 1 : 0) + (p[2] ? 1 : 0) + (p[3] ? 1 : 0);

    int x = cnt;
#pragma unroll
    for (int o = 1; o < 32; o <<= 1) {
        int y = __shfl_up_sync(0xffffffffu, x, o);
        if (lane >= o) x += y;
    }
    if (lane == 31) s_warp[w] = x;
    __syncthreads();
    if (t == 0) {
        int s = 0;
#pragma unroll
        for (int i = 0; i < 8; i++) { s_off[i] = s; s += s_warp[i]; }
        s_off[8] = s;
    }
    __syncthreads();
    int pos = s_off[w] + x - cnt;
#pragma unroll
    for (int i = 0; i < 4; i++) {
        if (p[i]) s_idx[pos++] = (unsigned short)(jb + i);
    }
    const int nnz = s_off[8];
    __syncthreads();

    // --- single pass: exp(leaky(ei+ej)) + per-head sum ---
    float4 ei4 = *(const float4*)(ei + (size_t)(b * N_ + n) * 4);
    float4 t4 = make_float4(0.f, 0.f, 0.f, 0.f);
    for (int k = t; k < nnz; k += 256) {
        int j = s_idx[k];
        float4 e4 = *(const float4*)(ej + (size_t)(b * N_ + j) * 4);
        e4.x += ei4.x; e4.y += ei4.y; e4.z += ei4.z; e4.w += ei4.w;
        e4.x = e4.x > 0.f ? e4.x : NEG_SLOPE * e4.x;
        e4.y = e4.y > 0.f ? e4.y : NEG_SLOPE * e4.y;
        e4.z = e4.z > 0.f ? e4.z : NEG_SLOPE * e4.z;
        e4.w = e4.w > 0.f ? e4.w : NEG_SLOPE * e4.w;
        e4.x = __expf(e4.x); e4.y = __expf(e4.y);
        e4.z = __expf(e4.z); e4.w = __expf(e4.w);
        t4.x += e4.x; t4.y += e4.y; t4.z += e4.z; t4.w += e4.w;
        ((float4*)s_e)[k] = e4;
    }
#pragma unroll
    for (int o = 16; o > 0; o >>= 1) {
        t4.x += __shfl_xor_sync(0xffffffffu, t4.x, o);
        t4.y += __shfl_xor_sync(0xffffffffu, t4.y, o);
        t4.z += __shfl_xor_sync(0xffffffffu, t4.z, o);
        t4.w += __shfl_xor_sync(0xffffffffu, t4.w, o);
    }
    if (lane == 0) s_wred[w] = t4;
    __syncthreads();
    if (t == 0) {
        float4 r = s_wred[0];
#pragma unroll
        for (int i = 1; i < 8; i++) {
            float4 v = s_wred[i];
            r.x += v.x; r.y += v.y; r.z += v.z; r.w += v.w;
        }
        s_bcast = r;
    }
    __syncthreads();
    float4 sm = s_bcast;

    // --- aggregation: 4 neighbor-groups x 64 threads, float4 columns ---
    const int g = t >> 6;        // neighbor stride group 0..3
    const int q = t & 63;        // column quad 0..63 (cols q*4..q*4+3)
    const int h = q >> 4;        // head of these 4 columns
    float4 acc = make_float4(0.f, 0.f, 0.f, 0.f);
    const float* WxB = Wx + (size_t)b * N_ * HD_ + q * 4;
#pragma unroll 4
    for (int k = g; k < nnz; k += 4) {
        int j = s_idx[k];
        float c = s_e[k * 4 + h];
        float4 wv = *(const float4*)(WxB + (size_t)j * HD_);
        acc.x += c * wv.x; acc.y += c * wv.y;
        acc.z += c * wv.z; acc.w += c * wv.w;
    }
    ((float4*)s_red)[t] = acc;
    __syncthreads();
    if (t < 64) {
        float4 a0 = ((float4*)s_red)[t];
        float4 a1 = ((float4*)s_red)[64 + t];
        float4 a2 = ((float4*)s_red)[128 + t];
        float4 a3 = ((float4*)s_red)[192 + t];
        const int hh = t >> 4;
        float sum_h = (hh == 0) ? sm.x : (hh == 1) ? sm.y : (hh == 2) ? sm.z : sm.w;
        float rs = 1.f / sum_h;
        float4 o;
        o.x = (a0.x + a1.x + a2.x + a3.x) * rs;
        o.y = (a0.y + a1.y + a2.y + a3.y) * rs;
        o.z = (a0.z + a1.z + a2.z + a3.z) * rs;
        o.w = (a0.w + a1.w + a2.w + a3.w) * rs;
        ((float4*)(out + (size_t)(b * N_ + n) * HD_))[t] = o;
    }
}

// ---------------------------------------------------------------------------
extern "C" void kernel_launch(void* const* d_in, const int* in_sizes, int n_in,
                              void* d_out, int out_size) {
    const float* x   = (const float*)d_in[0];   // (8,1024,256)
    const float* adj = (const float*)d_in[1];   // (8,1024,1024)
    const float* W   = (const float*)d_in[2];   // (256,256)
    const float* a   = (const float*)d_in[3];   // (1,4,128)
    float* out = (float*)d_out;

    float* Wx; cudaGetSymbolAddress((void**)&Wx, g_Wx);
    float* ei; cudaGetSymbolAddress((void**)&ei, g_ei);
    float* ej; cudaGetSymbolAddress((void**)&ej, g_ej);

    dim3 ggrid(B_ * N_ / 128, HD_ / 128);
    gemm_kernel<<<ggrid, 256>>>(x, W, Wx);
    eij_kernel<<<B_ * N_, 256>>>(a, Wx, ei, ej);
    gat_kernel<<<B_ * N_, 256>>>(adj, Wx, ei, ej, out);
}

// round 5
// speedup vs baseline: 1.1378x; 1.1378x over previous
#include <cuda_runtime.h>
#include <cuda_fp16.h>
#include <cuda_bf16.h>

#define B_ 8
#define N_ 1024
#define C_ 256
#define HD_ 256   // H*D
#define NEG_SLOPE 0.2f

struct alignas(8) half4 { __half2 a, b; };

// Scratch (no cudaMalloc allowed)
__device__ float  g_Wx [B_ * N_ * HD_];     // 32MB fp32 (for eij precision)
__device__ __half g_Wxh[B_ * N_ * HD_];     // 16MB fp16 (for aggregation gather)
__device__ float  g_ei [B_ * N_ * 4];
__device__ float  g_ej [B_ * N_ * 4];

// ---------------------------------------------------------------------------
// Kernel 1: Wx = x @ W   (M=8192, K=256, N=256)
// BM=128, BN=64, BK=32, 256 threads, TM=8, TN=4  (R1 measured-best config)
// Epilogue writes both fp32 and fp16 Wx.
// ---------------------------------------------------------------------------
__global__ void __launch_bounds__(256)
gemm_kernel(const float* __restrict__ A,
            const float* __restrict__ Bm,
            float* __restrict__ Cm,
            __half* __restrict__ Ch) {
    __shared__ float As[128][33];   // [m][k], pad 1 -> conflict-free
    __shared__ float Bs[32][64];    // [k][n]

    const int tid = threadIdx.x;
    const int rowBase = blockIdx.x * 128;
    const int colBase = blockIdx.y * 64;

    const int tx = tid & 15;        // 16 col groups * TN=4 -> 64
    const int ty = tid >> 4;        // 16 row groups * TM=8 -> 128

    const int ar0 = tid >> 3;
    const int af  = tid & 7;
    const int bkr = tid >> 3;

    float acc[8][4];
#pragma unroll
    for (int i = 0; i < 8; i++)
#pragma unroll
        for (int j = 0; j < 4; j++) acc[i][j] = 0.f;

    for (int kb = 0; kb < C_; kb += 32) {
#pragma unroll
        for (int i = 0; i < 4; i++) {
            int r = ar0 + 32 * i;
            float4 v = *(const float4*)(A + (size_t)(rowBase + r) * C_ + kb + af * 4);
            As[r][af * 4 + 0] = v.x;
            As[r][af * 4 + 1] = v.y;
            As[r][af * 4 + 2] = v.z;
            As[r][af * 4 + 3] = v.w;
        }
#pragma unroll
        for (int i = 0; i < 2; i++) {
            float4 v = *(const float4*)(Bm + (size_t)(kb + bkr) * HD_ + colBase + af * 8 + i * 4);
            *(float4*)(&Bs[bkr][af * 8 + i * 4]) = v;
        }
        __syncthreads();

#pragma unroll
        for (int k = 0; k < 32; k++) {
            float av[8];
#pragma unroll
            for (int i = 0; i < 8; i++) av[i] = As[ty * 8 + i][k];
            float4 bv = *(const float4*)(&Bs[k][tx * 4]);
#pragma unroll
            for (int i = 0; i < 8; i++) {
                acc[i][0] += av[i] * bv.x;
                acc[i][1] += av[i] * bv.y;
                acc[i][2] += av[i] * bv.z;
                acc[i][3] += av[i] * bv.w;
            }
        }
        __syncthreads();
    }
#pragma unroll
    for (int i = 0; i < 8; i++) {
        size_t off = (size_t)(rowBase + ty * 8 + i) * HD_ + colBase + tx * 4;
        *(float4*)(Cm + off) = make_float4(acc[i][0], acc[i][1], acc[i][2], acc[i][3]);
        half4 hv;
        hv.a = __floats2half2_rn(acc[i][0], acc[i][1]);
        hv.b = __floats2half2_rn(acc[i][2], acc[i][3]);
        *(half4*)(Ch + off) = hv;
    }
}

// ---------------------------------------------------------------------------
// Kernel 2: e_i/e_j projections (reads fp32 Wx).
// ---------------------------------------------------------------------------
__global__ void eij_kernel(const float* __restrict__ a,
                           const float* __restrict__ Wx,
                           float* __restrict__ ei, float* __restrict__ ej) {
    const int row = blockIdx.x;
    const int t = threadIdx.x;
    const int h = t >> 6, d = t & 63;

    float wx = Wx[(size_t)row * HD_ + t];
    float vi = wx * a[h * 128 + d];
    float vj = wx * a[h * 128 + 64 + d];

    const int lane = t & 31;
#pragma unroll
    for (int o = 16; o > 0; o >>= 1) {
        vi += __shfl_xor_sync(0xffffffffu, vi, o);
        vj += __shfl_xor_sync(0xffffffffu, vj, o);
    }
    __shared__ float si[8], sj[8];
    const int w = t >> 5;
    if (lane == 0) { si[w] = vi; sj[w] = vj; }
    __syncthreads();
    if (t < 4) {
        ei[row * 4 + t] = si[t * 2] + si[t * 2 + 1];
        ej[row * 4 + t] = sj[t * 2] + sj[t * 2 + 1];
    }
}

// ---------------------------------------------------------------------------
// Kernel 3: sparse-compact softmax + aggregation (fp16 gather).
// ---------------------------------------------------------------------------
__global__ void __launch_bounds__(256)
gat_kernel(const float* __restrict__ adj,
           const __half* __restrict__ Wxh,
           const float* __restrict__ ei,
           const float* __restrict__ ej,
           float* __restrict__ out) {
    const int b = blockIdx.x >> 10;
    const int n = blockIdx.x & 1023;
    const int t = threadIdx.x;
    const int lane = t & 31, w = t >> 5;

    __shared__ unsigned short s_idx[N_];
    __shared__ float s_e[N_ * 4];          // exp(e) per neighbor, 4 heads
    __shared__ float s_red[256 * 4];       // group partials (float4 view)
    __shared__ int   s_warp[8];
    __shared__ int   s_off[9];
    __shared__ float4 s_wred[8];
    __shared__ float4 s_bcast;

    const float* adj_row = adj + ((size_t)(b * N_ + n)) * N_;

    // --- deterministic compaction of nonzero neighbors (incl. self) ---
    const int jb = t * 4;
    float4 av4 = *(const float4*)(adj_row + jb);
    bool p[4];
    p[0] = (av4.x != 0.f) || (jb + 0 == n);
    p[1] = (av4.y != 0.f) || (jb + 1 == n);
    p[2] = (av4.z != 0.f) || (jb + 2 == n);
    p[3] = (av4.w != 0.f) || (jb + 3 == n);
    int cnt = (p[0] ? 1 : 0) + (p[1] ? 1 : 0) + (p[2] ? 1 : 0) + (p[3] ? 1 : 0);

    int x = cnt;
#pragma unroll
    for (int o = 1; o < 32; o <<= 1) {
        int y = __shfl_up_sync(0xffffffffu, x, o);
        if (lane >= o) x += y;
    }
    if (lane == 31) s_warp[w] = x;
    __syncthreads();
    if (t == 0) {
        int s = 0;
#pragma unroll
        for (int i = 0; i < 8; i++) { s_off[i] = s; s += s_warp[i]; }
        s_off[8] = s;
    }
    __syncthreads();
    int pos = s_off[w] + x - cnt;
#pragma unroll
    for (int i = 0; i < 4; i++) {
        if (p[i]) s_idx[pos++] = (unsigned short)(jb + i);
    }
    const int nnz = s_off[8];
    __syncthreads();

    // --- single pass: exp(leaky(ei+ej)) + per-head sum ---
    // (no max-subtraction: logits are O(5), exp cannot overflow; softmax is
    //  shift-invariant)
    float4 ei4 = *(const float4*)(ei + (size_t)(b * N_ + n) * 4);
    float4 t4 = make_float4(0.f, 0.f, 0.f, 0.f);
    for (int k = t; k < nnz; k += 256) {
        int j = s_idx[k];
        float4 e4 = *(const float4*)(ej + (size_t)(b * N_ + j) * 4);
        e4.x += ei4.x; e4.y += ei4.y; e4.z += ei4.z; e4.w += ei4.w;
        e4.x = e4.x > 0.f ? e4.x : NEG_SLOPE * e4.x;
        e4.y = e4.y > 0.f ? e4.y : NEG_SLOPE * e4.y;
        e4.z = e4.z > 0.f ? e4.z : NEG_SLOPE * e4.z;
        e4.w = e4.w > 0.f ? e4.w : NEG_SLOPE * e4.w;
        e4.x = __expf(e4.x); e4.y = __expf(e4.y);
        e4.z = __expf(e4.z); e4.w = __expf(e4.w);
        t4.x += e4.x; t4.y += e4.y; t4.z += e4.z; t4.w += e4.w;
        ((float4*)s_e)[k] = e4;
    }
#pragma unroll
    for (int o = 16; o > 0; o >>= 1) {
        t4.x += __shfl_xor_sync(0xffffffffu, t4.x, o);
        t4.y += __shfl_xor_sync(0xffffffffu, t4.y, o);
        t4.z += __shfl_xor_sync(0xffffffffu, t4.z, o);
        t4.w += __shfl_xor_sync(0xffffffffu, t4.w, o);
    }
    if (lane == 0) s_wred[w] = t4;
    __syncthreads();
    if (t == 0) {
        float4 r = s_wred[0];
#pragma unroll
        for (int i = 1; i < 8; i++) {
            float4 v = s_wred[i];
            r.x += v.x; r.y += v.y; r.z += v.z; r.w += v.w;
        }
        s_bcast = r;
    }
    __syncthreads();
    float4 sm = s_bcast;

    // --- aggregation: 4 neighbor-groups x 64 threads, 4 fp16 cols/thread ---
    const int g = t >> 6;        // neighbor stride group 0..3
    const int q = t & 63;        // column quad 0..63 (cols q*4..q*4+3)
    const int h = q >> 4;        // head of these 4 columns
    float4 acc = make_float4(0.f, 0.f, 0.f, 0.f);
    const __half* WxB = Wxh + (size_t)b * N_ * HD_ + q * 4;
#pragma unroll 4
    for (int k = g; k < nnz; k += 4) {
        int j = s_idx[k];
        float c = s_e[k * 4 + h];
        half4 rv = *(const half4*)(WxB + (size_t)j * HD_);   // 4 fp16 = 8B
        float2 f0 = __half22float2(rv.a);
        float2 f1 = __half22float2(rv.b);
        acc.x += c * f0.x; acc.y += c * f0.y;
        acc.z += c * f1.x; acc.w += c * f1.y;
    }
    ((float4*)s_red)[t] = acc;
    __syncthreads();
    if (t < 64) {
        float4 a0 = ((float4*)s_red)[t];
        float4 a1 = ((float4*)s_red)[64 + t];
        float4 a2 = ((float4*)s_red)[128 + t];
        float4 a3 = ((float4*)s_red)[192 + t];
        const int hh = t >> 4;
        float sum_h = (hh == 0) ? sm.x : (hh == 1) ? sm.y : (hh == 2) ? sm.z : sm.w;
        float rs = 1.f / sum_h;
        float4 o;
        o.x = (a0.x + a1.x + a2.x + a3.x) * rs;
        o.y = (a0.y + a1.y + a2.y + a3.y) * rs;
        o.z = (a0.z + a1.z + a2.z + a3.z) * rs;
        o.w = (a0.w + a1.w + a2.w + a3.w) * rs;
        ((float4*)(out + (size_t)(b * N_ + n) * HD_))[t] = o;
    }
}

// ---------------------------------------------------------------------------
extern "C" void kernel_launch(void* const* d_in, const int* in_sizes, int n_in,
                              void* d_out, int out_size) {
    const float* x   = (const float*)d_in[0];   // (8,1024,256)
    const float* adj = (const float*)d_in[1];   // (8,1024,1024)
    const float* W   = (const float*)d_in[2];   // (256,256)
    const float* a   = (const float*)d_in[3];   // (1,4,128)
    float* out = (float*)d_out;

    float*  Wx;  cudaGetSymbolAddress((void**)&Wx,  g_Wx);
    __half* Wxh; cudaGetSymbolAddress((void**)&Wxh, g_Wxh);
    float*  ei;  cudaGetSymbolAddress((void**)&ei,  g_ei);
    float*  ej;  cudaGetSymbolAddress((void**)&ej,  g_ej);

    dim3 ggrid(B_ * N_ / 128, HD_ / 64);
    gemm_kernel<<<ggrid, 256>>>(x, W, Wx, Wxh);
    eij_kernel<<<B_ * N_, 256>>>(a, Wx, ei, ej);
    gat_kernel<<<B_ * N_, 256>>>(adj, Wxh, ei, ej, out);
}